// round 2
// baseline (speedup 1.0000x reference)
#include <cuda_runtime.h>
#include <math_constants.h>

#define NB 8
#define NL 2048
#define ND 1024

// ---------------- scratch (device globals: no allocation allowed) ----------
__device__ float g_qp[NB * NL * ND];                       // 64 MB
__device__ float g_kp[NB * NL * ND];                       // 64 MB
__device__ float g_vp[NB * NL * ND];                       // 64 MB
__device__ float g_att[(size_t)NB * NL * NL];              // 128 MB
__device__ float g_ao[NB * NL * ND];                       // 64 MB
__device__ float g_x[NB * NL * ND];                        // 64 MB
__device__ unsigned char g_kmask[NB * NL];
__device__ unsigned char g_qmask[NB * NL];

// ---------------- padding masks from raw q/k (rowsum == 0) -----------------
__global__ __launch_bounds__(256)
void mask_kernel(const float* __restrict__ q, const float* __restrict__ k,
                 unsigned char* __restrict__ qm, unsigned char* __restrict__ km) {
    int r = blockIdx.x;                       // 0 .. NB*NL-1
    int tid = threadIdx.x;
    const float4* qr = (const float4*)(q + (long long)r * ND);
    const float4* kr = (const float4*)(k + (long long)r * ND);
    float sq = 0.f, sk = 0.f;
    for (int i = tid; i < ND / 4; i += 256) {
        float4 a = qr[i]; sq += (a.x + a.y) + (a.z + a.w);
        float4 b = kr[i]; sk += (b.x + b.y) + (b.z + b.w);
    }
    __shared__ float rq[256], rk[256];
    rq[tid] = sq; rk[tid] = sk;
    __syncthreads();
    for (int s = 128; s > 0; s >>= 1) {
        if (tid < s) { rq[tid] += rq[tid + s]; rk[tid] += rk[tid + s]; }
        __syncthreads();
    }
    if (tid == 0) {
        qm[r] = (rq[0] == 0.0f) ? 1 : 0;
        km[r] = (rk[0] == 0.0f) ? 1 : 0;
    }
}

// ---------------- SGEMM: 128x128x8 tile, 8x8 microtile, 256 threads --------
// BT=true : C[m,n] = alpha * sum_k A[m,k]*B[n,k]   (B row-major [N,K], "NT")
// BT=false: C[m,n] = alpha * sum_k A[m,k]*B[k,n]   (B row-major [K,N], "NN")
// Optional bias[n] and residual[m*N+n]. All dims assumed multiples of tiles.
template <bool BT>
__global__ __launch_bounds__(256)
void sgemm_kernel(const float* __restrict__ A, const float* __restrict__ Bm,
                  const float* __restrict__ bias, const float* __restrict__ res,
                  float* __restrict__ C,
                  int M, int N, int K,
                  long long sA, long long sB, long long sC,
                  float alpha) {
    const int BM = 128, BN = 128, BK = 8, TM = 8, TN = 8;
    __shared__ float As[BK][BM];
    __shared__ float Bs[BK][BN];

    int bz = blockIdx.z;
    A += (long long)bz * sA;
    Bm += (long long)bz * sB;
    C += (long long)bz * sC;

    int m0 = blockIdx.y * BM;
    int n0 = blockIdx.x * BN;
    int tid = threadIdx.x;
    int tx = tid & 15;        // 0..15
    int ty = tid >> 4;        // 0..15

    // global load indices
    int aRow = tid >> 1;            // 0..127
    int aCol = (tid & 1) * 4;       // 0 or 4
    int bRowNN = tid >> 5;          // 0..7
    int bColNN = (tid & 31) * 4;    // 0..124

    float acc[TM][TN];
#pragma unroll
    for (int i = 0; i < TM; i++)
#pragma unroll
        for (int j = 0; j < TN; j++) acc[i][j] = 0.0f;

    for (int k0 = 0; k0 < K; k0 += BK) {
        float4 av = *(const float4*)(A + (long long)(m0 + aRow) * K + k0 + aCol);
        As[aCol + 0][aRow] = av.x;
        As[aCol + 1][aRow] = av.y;
        As[aCol + 2][aRow] = av.z;
        As[aCol + 3][aRow] = av.w;
        if (BT) {
            float4 bv = *(const float4*)(Bm + (long long)(n0 + aRow) * K + k0 + aCol);
            Bs[aCol + 0][aRow] = bv.x;
            Bs[aCol + 1][aRow] = bv.y;
            Bs[aCol + 2][aRow] = bv.z;
            Bs[aCol + 3][aRow] = bv.w;
        } else {
            float4 bv = *(const float4*)(Bm + (long long)(k0 + bRowNN) * N + n0 + bColNN);
            *(float4*)&Bs[bRowNN][bColNN] = bv;
        }
        __syncthreads();
#pragma unroll
        for (int kk = 0; kk < BK; kk++) {
            float ra[TM], rb[TN];
#pragma unroll
            for (int i = 0; i < TM; i++) ra[i] = As[kk][ty * TM + i];
#pragma unroll
            for (int j = 0; j < TN; j++) rb[j] = Bs[kk][tx * TN + j];
#pragma unroll
            for (int i = 0; i < TM; i++)
#pragma unroll
                for (int j = 0; j < TN; j++) acc[i][j] += ra[i] * rb[j];
        }
        __syncthreads();
    }

    // epilogue
#pragma unroll
    for (int i = 0; i < TM; i++) {
        int m = m0 + ty * TM + i;
#pragma unroll
        for (int j = 0; j < TN; j++) {
            int n = n0 + tx * TN + j;
            float c = acc[i][j] * alpha;
            if (bias) c += bias[n];
            if (res)  c += res[(long long)m * N + n];
            C[(long long)m * N + n] = c;
        }
    }
}

// ---------------- masked softmax over rows of att [B, L, L] ----------------
__global__ __launch_bounds__(256)
void softmax_kernel(float* __restrict__ att,
                    const unsigned char* __restrict__ km,
                    const unsigned char* __restrict__ qm) {
    int i = blockIdx.x;
    int b = blockIdx.y;
    int tid = threadIdx.x;
    float* row = att + ((long long)b * NL + i) * NL;
    const unsigned char* kmb = km + b * NL;
    bool qz = qm[b * NL + i] != 0;

    float vals[NL / 256];
    float mx = -CUDART_INF_F;
#pragma unroll
    for (int t = 0; t < NL / 256; t++) {
        int j = tid + t * 256;
        float v = kmb[j] ? -CUDART_INF_F : row[j];
        vals[t] = v;
        mx = fmaxf(mx, v);
    }
    __shared__ float red[256];
    red[tid] = mx;
    __syncthreads();
    for (int s = 128; s > 0; s >>= 1) {
        if (tid < s) red[tid] = fmaxf(red[tid], red[tid + s]);
        __syncthreads();
    }
    mx = red[0];
    __syncthreads();

    float sum = 0.f;
#pragma unroll
    for (int t = 0; t < NL / 256; t++) {
        float e = __expf(vals[t] - mx);   // exp(-inf) = 0 for masked keys
        vals[t] = e;
        sum += e;
    }
    red[tid] = sum;
    __syncthreads();
    for (int s = 128; s > 0; s >>= 1) {
        if (tid < s) red[tid] += red[tid + s];
        __syncthreads();
    }
    float inv = 1.0f / red[0];
#pragma unroll
    for (int t = 0; t < NL / 256; t++) {
        int j = tid + t * 256;
        row[j] = qz ? 0.0f : vals[t] * inv;
    }
}

// ---------------- LayerNorm (no affine), row length 1024 -------------------
__global__ __launch_bounds__(256)
void layernorm_kernel(const float* __restrict__ x, float* __restrict__ out) {
    int r = blockIdx.x;
    int tid = threadIdx.x;
    const float4* xr = (const float4*)(x + (long long)r * ND);
    float4 v = xr[tid];                    // 256 * 4 == 1024 exactly
    __shared__ float red[256];

    red[tid] = (v.x + v.y) + (v.z + v.w);
    __syncthreads();
    for (int s = 128; s > 0; s >>= 1) {
        if (tid < s) red[tid] += red[tid + s];
        __syncthreads();
    }
    float mu = red[0] * (1.0f / ND);
    __syncthreads();

    float dx = v.x - mu, dy = v.y - mu, dz = v.z - mu, dw = v.w - mu;
    red[tid] = dx * dx + dy * dy + dz * dz + dw * dw;
    __syncthreads();
    for (int s = 128; s > 0; s >>= 1) {
        if (tid < s) red[tid] += red[tid + s];
        __syncthreads();
    }
    float inv = rsqrtf(red[0] * (1.0f / ND) + 1e-5f);

    float4 o;
    o.x = dx * inv; o.y = dy * inv; o.z = dz * inv; o.w = dw * inv;
    ((float4*)(out + (long long)r * ND))[tid] = o;
}

// ---------------- launch ---------------------------------------------------
extern "C" void kernel_launch(void* const* d_in, const int* in_sizes, int n_in,
                              void* d_out, int out_size) {
    const float* q  = (const float*)d_in[0];
    const float* k  = (const float*)d_in[1];
    const float* v  = (const float*)d_in[2];
    const float* Wq = (const float*)d_in[3];
    const float* bq = (const float*)d_in[4];
    const float* Wk = (const float*)d_in[5];
    const float* bk = (const float*)d_in[6];
    const float* Wv = (const float*)d_in[7];
    const float* bv = (const float*)d_in[8];
    const float* Wo = (const float*)d_in[9];
    const float* bo = (const float*)d_in[10];
    float* out = (float*)d_out;

    float *qp, *kp, *vp, *att, *ao, *x;
    unsigned char *km, *qm;
    cudaGetSymbolAddress((void**)&qp,  g_qp);
    cudaGetSymbolAddress((void**)&kp,  g_kp);
    cudaGetSymbolAddress((void**)&vp,  g_vp);
    cudaGetSymbolAddress((void**)&att, g_att);
    cudaGetSymbolAddress((void**)&ao,  g_ao);
    cudaGetSymbolAddress((void**)&x,   g_x);
    cudaGetSymbolAddress((void**)&km,  g_kmask);
    cudaGetSymbolAddress((void**)&qm,  g_qmask);

    const int M = NB * NL;                     // 16384
    const long long sQK = (long long)NL * ND;  // per-batch stride of qp/kp/vp
    const long long sAT = (long long)NL * NL;  // per-batch stride of att
    const float scale = 0.03125f;              // 1024^-0.5

    // masks from raw q/k
    mask_kernel<<<M, 256>>>(q, k, qm, km);

    // projections: y = x @ W^T + b   (torch Linear semantics)
    sgemm_kernel<true><<<dim3(ND / 128, M / 128, 1), 256>>>(
        q, Wq, bq, nullptr, qp, M, ND, ND, 0, 0, 0, 1.0f);
    sgemm_kernel<true><<<dim3(ND / 128, M / 128, 1), 256>>>(
        k, Wk, bk, nullptr, kp, M, ND, ND, 0, 0, 0, 1.0f);
    sgemm_kernel<true><<<dim3(ND / 128, M / 128, 1), 256>>>(
        v, Wv, bv, nullptr, vp, M, ND, ND, 0, 0, 0, 1.0f);

    // scores: att[b] = scale * qp[b] @ kp[b]^T
    sgemm_kernel<true><<<dim3(NL / 128, NL / 128, NB), 256>>>(
        qp, kp, nullptr, nullptr, att, NL, NL, ND, sQK, sQK, sAT, scale);

    // masked softmax
    softmax_kernel<<<dim3(NL, NB), 256>>>(att, km, qm);

    // context: ao[b] = att[b] @ vp[b]
    sgemm_kernel<false><<<dim3(ND / 128, NL / 128, NB), 256>>>(
        att, vp, nullptr, nullptr, ao, NL, ND, NL, sAT, sQK, sQK, 1.0f);

    // output projection + bias + residual (projected q)
    sgemm_kernel<true><<<dim3(ND / 128, M / 128, 1), 256>>>(
        ao, Wo, bo, qp, x, M, ND, ND, 0, 0, 0, 1.0f);

    // LayerNorm -> final output
    layernorm_kernel<<<M, 256>>>(x, out);
}

// round 4
// speedup vs baseline: 3.3098x; 3.3098x over previous
#include <cuda_runtime.h>
#include <cuda_bf16.h>
#include <math_constants.h>
#include <cstdint>

#define NB 8
#define NL 2048
#define ND 1024

typedef __nv_bfloat16 bf16;

// ------------------------------ scratch ------------------------------------
__device__ bf16  g_qh[NB * NL * ND],  g_ql[NB * NL * ND];
__device__ bf16  g_kh[NB * NL * ND],  g_kl[NB * NL * ND];
__device__ bf16  g_vh[NB * NL * ND],  g_vl[NB * NL * ND];
__device__ bf16  g_Wqh[ND * ND], g_Wql[ND * ND];
__device__ bf16  g_Wkh[ND * ND], g_Wkl[ND * ND];
__device__ bf16  g_Wvh[ND * ND], g_Wvl[ND * ND];
__device__ bf16  g_Woh[ND * ND], g_Wol[ND * ND];
__device__ float g_qp[NB * NL * ND];
__device__ bf16  g_qph[NB * NL * ND], g_qpl[NB * NL * ND];
__device__ bf16  g_kph[NB * NL * ND], g_kpl[NB * NL * ND];
__device__ bf16  g_vph[NB * NL * ND], g_vpl[NB * NL * ND];
__device__ bf16  g_vpth[NB * NL * ND], g_vptl[NB * NL * ND];
__device__ float g_att[(size_t)NB * NL * NL];
__device__ bf16  g_atth[(size_t)NB * NL * NL], g_attl[(size_t)NB * NL * NL];
__device__ bf16  g_aoh[NB * NL * ND], g_aol[NB * NL * ND];
__device__ float g_x[NB * NL * ND];
__device__ unsigned char g_kmask[NB * NL];
__device__ unsigned char g_qmask[NB * NL];

// ------------------------------ helpers ------------------------------------
__device__ __forceinline__ uint32_t smem_u32(const void* p) {
    uint32_t a;
    asm("{ .reg .u64 t; cvta.to.shared.u64 t, %1; cvt.u32.u64 %0, t; }"
        : "=r"(a) : "l"(p));
    return a;
}

__device__ __forceinline__ void cpasync16(uint32_t dst, const void* src) {
    asm volatile("cp.async.cg.shared.global [%0], [%1], 16;" :: "r"(dst), "l"(src));
}

__device__ __forceinline__ void ldsm4(uint32_t* r, uint32_t addr) {
    asm volatile("ldmatrix.sync.aligned.m8n8.x4.shared.b16 {%0,%1,%2,%3}, [%4];"
                 : "=r"(r[0]), "=r"(r[1]), "=r"(r[2]), "=r"(r[3]) : "r"(addr));
}

__device__ __forceinline__ void mma16816(float* d, const uint32_t* a, const uint32_t* b) {
    asm volatile(
        "mma.sync.aligned.m16n8k16.row.col.f32.bf16.bf16.f32 "
        "{%0,%1,%2,%3}, {%4,%5,%6,%7}, {%8,%9}, {%0,%1,%2,%3};"
        : "+f"(d[0]), "+f"(d[1]), "+f"(d[2]), "+f"(d[3])
        : "r"(a[0]), "r"(a[1]), "r"(a[2]), "r"(a[3]), "r"(b[0]), "r"(b[1]));
}

// ------------------------------ GEMM ---------------------------------------
// C[M,N] = alpha * (Ahi+Alo)[M,K] @ (Bhi+Blo)[N,K]^T   (3-term bf16 split)
// CTA tile 128x128, BK=64, 8 warps (2x4), warp tile 64x32, mma m16n8k16.
#define STG_A_H 0u
#define STG_A_L 16384u
#define STG_B_H 32768u
#define STG_B_L 49152u
#define STG_BYTES 65536u
#define GEMM_SMEM (2u * STG_BYTES)

__device__ __forceinline__ void load_stage(
    const bf16* __restrict__ Ah, const bf16* __restrict__ Al,
    const bf16* __restrict__ Bh, const bf16* __restrict__ Bl,
    int K, long long m0, long long n0, long long kb, uint32_t sb, int tid) {
#pragma unroll
    for (int i = 0; i < 4; i++) {
        int idx = tid + i * 256;
        int row = idx >> 3, ch = idx & 7;
        uint32_t sw = (uint32_t)(row * 128 + ((ch ^ (row & 7)) << 4));
        long long ga = (m0 + row) * K + kb + ch * 8;
        cpasync16(sb + STG_A_H + sw, Ah + ga);
        cpasync16(sb + STG_A_L + sw, Al + ga);
        long long gb = (n0 + row) * K + kb + ch * 8;
        cpasync16(sb + STG_B_H + sw, Bh + gb);
        cpasync16(sb + STG_B_L + sw, Bl + gb);
    }
    asm volatile("cp.async.commit_group;" ::: "memory");
}

__global__ __launch_bounds__(256, 1)
void gemm_kernel(const bf16* __restrict__ Ah, const bf16* __restrict__ Al, long long sA,
                 const bf16* __restrict__ Bh, const bf16* __restrict__ Bl, long long sB,
                 float* __restrict__ Cf, bf16* __restrict__ Ch, bf16* __restrict__ Cl,
                 long long sC,
                 const float* __restrict__ bias, const float* __restrict__ res,
                 int K, int ldC, float alpha) {
    extern __shared__ char dsm[];
    const uint32_t sb0 = smem_u32(dsm);
    const int tid = threadIdx.x;
    const int lane = tid & 31, wid = tid >> 5;
    const int warp_m = wid >> 2, warp_n = wid & 3;
    const int bz = blockIdx.z;
    Ah += (long long)bz * sA;  Al += (long long)bz * sA;
    Bh += (long long)bz * sB;  Bl += (long long)bz * sB;
    const long long coff = (long long)bz * sC;
    const long long m0 = (long long)blockIdx.y * 128;
    const long long n0 = (long long)blockIdx.x * 128;

    float acc[4][4][4];
#pragma unroll
    for (int a = 0; a < 4; a++)
#pragma unroll
        for (int b = 0; b < 4; b++)
#pragma unroll
            for (int c = 0; c < 4; c++) acc[a][b][c] = 0.0f;

    const int nc = K >> 6;
    load_stage(Ah, Al, Bh, Bl, K, m0, n0, 0, sb0, tid);

    // lane-invariant fragment addressing
    const int aRow = warp_m * 64 + ((lane >> 3) & 1) * 8 + (lane & 7);
    const int aSel = lane >> 4;          // 0/1 -> k chunk
    const int bRow = warp_n * 32 + (lane >> 4) * 8 + (lane & 7);
    const int bSel = (lane >> 3) & 1;    // 0/1 -> k chunk

    for (int c = 0; c < nc; c++) {
        const uint32_t sb = sb0 + (uint32_t)(c & 1) * STG_BYTES;
        if (c + 1 < nc) {
            load_stage(Ah, Al, Bh, Bl, K, m0, n0, (long long)(c + 1) * 64,
                       sb0 + (uint32_t)((c + 1) & 1) * STG_BYTES, tid);
            asm volatile("cp.async.wait_group 1;" ::: "memory");
        } else {
            asm volatile("cp.async.wait_group 0;" ::: "memory");
        }
        __syncthreads();

#pragma unroll
        for (int s = 0; s < 4; s++) {
            uint32_t ah[4][4], al[4][4], bh[2][4], bl[2][4];
#pragma unroll
            for (int mt = 0; mt < 4; mt++) {
                int r = aRow + mt * 16;
                uint32_t a = sb + (uint32_t)(r * 128 + (((2 * s + aSel) ^ (r & 7)) << 4));
                ldsm4(ah[mt], a + STG_A_H);
                ldsm4(al[mt], a + STG_A_L);
            }
#pragma unroll
            for (int p = 0; p < 2; p++) {
                int r = bRow + p * 16;
                uint32_t a = sb + (uint32_t)(r * 128 + (((2 * s + bSel) ^ (r & 7)) << 4));
                ldsm4(bh[p], a + STG_B_H);
                ldsm4(bl[p], a + STG_B_L);
            }
#pragma unroll
            for (int mt = 0; mt < 4; mt++)
#pragma unroll
                for (int nt = 0; nt < 4; nt++) {
                    const uint32_t* Bhp = &bh[nt >> 1][(nt & 1) * 2];
                    const uint32_t* Blp = &bl[nt >> 1][(nt & 1) * 2];
                    mma16816(acc[mt][nt], ah[mt], Bhp);   // hi*hi
                    mma16816(acc[mt][nt], ah[mt], Blp);   // hi*lo
                    mma16816(acc[mt][nt], al[mt], Bhp);   // lo*hi
                }
        }
        __syncthreads();
    }

    // ---------------- epilogue -------------------------------------------
    const int g = lane >> 2, t = lane & 3;
#pragma unroll
    for (int mt = 0; mt < 4; mt++) {
#pragma unroll
        for (int nt = 0; nt < 4; nt++) {
            float* d = acc[mt][nt];
            int row0 = (int)m0 + warp_m * 64 + mt * 16 + g;
            int col  = (int)n0 + warp_n * 32 + nt * 8 + t * 2;
            float v0 = d[0] * alpha, v1 = d[1] * alpha;
            float v2 = d[2] * alpha, v3 = d[3] * alpha;
            if (bias) {
                float b0 = bias[col], b1 = bias[col + 1];
                v0 += b0; v1 += b1; v2 += b0; v3 += b1;
            }
            long long o0 = coff + (long long)row0 * ldC + col;
            long long o1 = o0 + 8LL * ldC;
            if (res) {
                v0 += res[o0]; v1 += res[o0 + 1];
                v2 += res[o1]; v3 += res[o1 + 1];
            }
            if (Cf) {
                *(float2*)(Cf + o0) = make_float2(v0, v1);
                *(float2*)(Cf + o1) = make_float2(v2, v3);
            }
            if (Ch) {
                __nv_bfloat162 h0, h1, l0, l1;
                h0.x = __float2bfloat16(v0); h0.y = __float2bfloat16(v1);
                h1.x = __float2bfloat16(v2); h1.y = __float2bfloat16(v3);
                l0.x = __float2bfloat16(v0 - __bfloat162float(h0.x));
                l0.y = __float2bfloat16(v1 - __bfloat162float(h0.y));
                l1.x = __float2bfloat16(v2 - __bfloat162float(h1.x));
                l1.y = __float2bfloat16(v3 - __bfloat162float(h1.y));
                *(__nv_bfloat162*)(Ch + o0) = h0;
                *(__nv_bfloat162*)(Ch + o1) = h1;
                *(__nv_bfloat162*)(Cl + o0) = l0;
                *(__nv_bfloat162*)(Cl + o1) = l1;
            }
        }
    }
}

// ---------------- fp32 -> bf16 hi/lo split ---------------------------------
__global__ __launch_bounds__(256)
void split_kernel(const float* __restrict__ x, bf16* __restrict__ h,
                  bf16* __restrict__ l, long long n) {
    long long i = ((long long)blockIdx.x * 256 + threadIdx.x) * 4;
    if (i >= n) return;
    float4 v = *(const float4*)(x + i);
    bf16 hh[4], ll[4];
    float vv[4] = {v.x, v.y, v.z, v.w};
#pragma unroll
    for (int j = 0; j < 4; j++) {
        hh[j] = __float2bfloat16(vv[j]);
        ll[j] = __float2bfloat16(vv[j] - __bfloat162float(hh[j]));
    }
    *(uint2*)(h + i) = *(uint2*)hh;
    *(uint2*)(l + i) = *(uint2*)ll;
}

// ---------------- masks from raw q/k (rowsum == 0) --------------------------
__global__ __launch_bounds__(256)
void mask_kernel(const float* __restrict__ q, const float* __restrict__ k,
                 unsigned char* __restrict__ qm, unsigned char* __restrict__ km) {
    int r = blockIdx.x;
    int tid = threadIdx.x;
    const float4* qr = (const float4*)(q + (long long)r * ND);
    const float4* kr = (const float4*)(k + (long long)r * ND);
    float sq = 0.f, sk = 0.f;
    for (int i = tid; i < ND / 4; i += 256) {
        float4 a = qr[i]; sq += (a.x + a.y) + (a.z + a.w);
        float4 b = kr[i]; sk += (b.x + b.y) + (b.z + b.w);
    }
    __shared__ float rq[256], rk[256];
    rq[tid] = sq; rk[tid] = sk;
    __syncthreads();
    for (int s = 128; s > 0; s >>= 1) {
        if (tid < s) { rq[tid] += rq[tid + s]; rk[tid] += rk[tid + s]; }
        __syncthreads();
    }
    if (tid == 0) {
        qm[r] = (rq[0] == 0.0f) ? 1 : 0;
        km[r] = (rk[0] == 0.0f) ? 1 : 0;
    }
}

// ---------------- masked softmax + bf16 split output ------------------------
__global__ __launch_bounds__(256)
void softmax_kernel(const float* __restrict__ att,
                    bf16* __restrict__ atth, bf16* __restrict__ attl,
                    const unsigned char* __restrict__ km,
                    const unsigned char* __restrict__ qm) {
    int i = blockIdx.x;
    int b = blockIdx.y;
    int tid = threadIdx.x;
    const float* row = att + ((long long)b * NL + i) * NL;
    bf16* oh = atth + ((long long)b * NL + i) * NL;
    bf16* ol = attl + ((long long)b * NL + i) * NL;
    const unsigned char* kmb = km + b * NL;
    bool qz = qm[b * NL + i] != 0;

    float vals[NL / 256];
    float mx = -CUDART_INF_F;
#pragma unroll
    for (int t = 0; t < NL / 256; t++) {
        int j = tid + t * 256;
        float v = kmb[j] ? -CUDART_INF_F : row[j];
        vals[t] = v;
        mx = fmaxf(mx, v);
    }
    __shared__ float red[256];
    red[tid] = mx;
    __syncthreads();
    for (int s = 128; s > 0; s >>= 1) {
        if (tid < s) red[tid] = fmaxf(red[tid], red[tid + s]);
        __syncthreads();
    }
    mx = red[0];
    __syncthreads();

    float sum = 0.f;
#pragma unroll
    for (int t = 0; t < NL / 256; t++) {
        float e = __expf(vals[t] - mx);
        vals[t] = e;
        sum += e;
    }
    red[tid] = sum;
    __syncthreads();
    for (int s = 128; s > 0; s >>= 1) {
        if (tid < s) red[tid] += red[tid + s];
        __syncthreads();
    }
    float inv = 1.0f / red[0];
#pragma unroll
    for (int t = 0; t < NL / 256; t++) {
        int j = tid + t * 256;
        float v = qz ? 0.0f : vals[t] * inv;
        bf16 h = __float2bfloat16(v);
        bf16 l = __float2bfloat16(v - __bfloat162float(h));
        oh[j] = h;
        ol[j] = l;
    }
}

// ---------------- per-batch transpose of vp hi/lo ---------------------------
__global__ __launch_bounds__(256)
void transpose_kernel(const bf16* __restrict__ h, const bf16* __restrict__ l,
                      bf16* __restrict__ th, bf16* __restrict__ tl) {
    __shared__ bf16 sh[32][33], sl[32][33];
    int b = blockIdx.z;
    int n0 = blockIdx.x * 32;
    int l0 = blockIdx.y * 32;
    int tx = threadIdx.x & 31;
    int ty = threadIdx.x >> 5;   // 0..7
#pragma unroll
    for (int i = 0; i < 4; i++) {
        int r = ty + i * 8;
        long long src = ((long long)b * NL + l0 + r) * ND + n0 + tx;
        sh[r][tx] = h[src];
        sl[r][tx] = l[src];
    }
    __syncthreads();
#pragma unroll
    for (int i = 0; i < 4; i++) {
        int r = ty + i * 8;
        long long dst = (long long)b * ND * NL + (long long)(n0 + r) * NL + l0 + tx;
        th[dst] = sh[tx][r];
        tl[dst] = sl[tx][r];
    }
}

// ---------------- LayerNorm (no affine), row length 1024 --------------------
__global__ __launch_bounds__(256)
void layernorm_kernel(const float* __restrict__ x, float* __restrict__ out) {
    int r = blockIdx.x;
    int tid = threadIdx.x;
    const float4* xr = (const float4*)(x + (long long)r * ND);
    float4 v = xr[tid];
    __shared__ float red[256];

    red[tid] = (v.x + v.y) + (v.z + v.w);
    __syncthreads();
    for (int s = 128; s > 0; s >>= 1) {
        if (tid < s) red[tid] += red[tid + s];
        __syncthreads();
    }
    float mu = red[0] * (1.0f / ND);
    __syncthreads();

    float dx = v.x - mu, dy = v.y - mu, dz = v.z - mu, dw = v.w - mu;
    red[tid] = dx * dx + dy * dy + dz * dz + dw * dw;
    __syncthreads();
    for (int s = 128; s > 0; s >>= 1) {
        if (tid < s) red[tid] += red[tid + s];
        __syncthreads();
    }
    float inv = rsqrtf(red[0] * (1.0f / ND) + 1e-5f);

    float4 o;
    o.x = dx * inv; o.y = dy * inv; o.z = dz * inv; o.w = dw * inv;
    ((float4*)(out + (long long)r * ND))[tid] = o;
}

// ---------------- launch -----------------------------------------------------
extern "C" void kernel_launch(void* const* d_in, const int* in_sizes, int n_in,
                              void* d_out, int out_size) {
    const float* q  = (const float*)d_in[0];
    const float* k  = (const float*)d_in[1];
    const float* v  = (const float*)d_in[2];
    const float* Wq = (const float*)d_in[3];
    const float* bq = (const float*)d_in[4];
    const float* Wk = (const float*)d_in[5];
    const float* bk = (const float*)d_in[6];
    const float* Wv = (const float*)d_in[7];
    const float* bv = (const float*)d_in[8];
    const float* Wo = (const float*)d_in[9];
    const float* bo = (const float*)d_in[10];
    float* out = (float*)d_out;

    bf16 *qh, *ql, *kh, *kl, *vh, *vl;
    bf16 *Wqh, *Wql, *Wkh, *Wkl, *Wvh, *Wvl, *Woh, *Wol;
    float *qp, *att, *x;
    bf16 *qph, *qpl, *kph, *kpl, *vph, *vpl, *vpth, *vptl, *atth, *attl, *aoh, *aol;
    unsigned char *km, *qm;
    cudaGetSymbolAddress((void**)&qh,  g_qh);   cudaGetSymbolAddress((void**)&ql,  g_ql);
    cudaGetSymbolAddress((void**)&kh,  g_kh);   cudaGetSymbolAddress((void**)&kl,  g_kl);
    cudaGetSymbolAddress((void**)&vh,  g_vh);   cudaGetSymbolAddress((void**)&vl,  g_vl);
    cudaGetSymbolAddress((void**)&Wqh, g_Wqh);  cudaGetSymbolAddress((void**)&Wql, g_Wql);
    cudaGetSymbolAddress((void**)&Wkh, g_Wkh);  cudaGetSymbolAddress((void**)&Wkl, g_Wkl);
    cudaGetSymbolAddress((void**)&Wvh, g_Wvh);  cudaGetSymbolAddress((void**)&Wvl, g_Wvl);
    cudaGetSymbolAddress((void**)&Woh, g_Woh);  cudaGetSymbolAddress((void**)&Wol, g_Wol);
    cudaGetSymbolAddress((void**)&qp,  g_qp);
    cudaGetSymbolAddress((void**)&qph, g_qph);  cudaGetSymbolAddress((void**)&qpl, g_qpl);
    cudaGetSymbolAddress((void**)&kph, g_kph);  cudaGetSymbolAddress((void**)&kpl, g_kpl);
    cudaGetSymbolAddress((void**)&vph, g_vph);  cudaGetSymbolAddress((void**)&vpl, g_vpl);
    cudaGetSymbolAddress((void**)&vpth, g_vpth); cudaGetSymbolAddress((void**)&vptl, g_vptl);
    cudaGetSymbolAddress((void**)&att, g_att);
    cudaGetSymbolAddress((void**)&atth, g_atth); cudaGetSymbolAddress((void**)&attl, g_attl);
    cudaGetSymbolAddress((void**)&aoh, g_aoh);  cudaGetSymbolAddress((void**)&aol, g_aol);
    cudaGetSymbolAddress((void**)&x,   g_x);
    cudaGetSymbolAddress((void**)&km,  g_kmask); cudaGetSymbolAddress((void**)&qm, g_qmask);

    cudaFuncSetAttribute(gemm_kernel, cudaFuncAttributeMaxDynamicSharedMemorySize, GEMM_SMEM);

    const long long E  = (long long)NB * NL * ND;   // 16,777,216
    const long long EW = (long long)ND * ND;        // 1,048,576
    const int M = NB * NL;                          // 16384
    const long long sQK = (long long)NL * ND;
    const long long sAT = (long long)NL * NL;
    const float scale = 0.03125f;                   // 1024^-0.5

    // masks
    mask_kernel<<<M, 256>>>(q, k, qm, km);

    // fp32 -> bf16 hi/lo splits of inputs and weights
    split_kernel<<<(int)(E / 4 / 256), 256>>>(q, qh, ql, E);
    split_kernel<<<(int)(E / 4 / 256), 256>>>(k, kh, kl, E);
    split_kernel<<<(int)(E / 4 / 256), 256>>>(v, vh, vl, E);
    split_kernel<<<(int)(EW / 4 / 256), 256>>>(Wq, Wqh, Wql, EW);
    split_kernel<<<(int)(EW / 4 / 256), 256>>>(Wk, Wkh, Wkl, EW);
    split_kernel<<<(int)(EW / 4 / 256), 256>>>(Wv, Wvh, Wvl, EW);
    split_kernel<<<(int)(EW / 4 / 256), 256>>>(Wo, Woh, Wol, EW);

    // projections: y = x @ W^T + b
    gemm_kernel<<<dim3(ND / 128, M / 128, 1), 256, GEMM_SMEM>>>(
        qh, ql, 0, Wqh, Wql, 0, qp, qph, qpl, 0, bq, nullptr, ND, ND, 1.0f);
    gemm_kernel<<<dim3(ND / 128, M / 128, 1), 256, GEMM_SMEM>>>(
        kh, kl, 0, Wkh, Wkl, 0, nullptr, kph, kpl, 0, bk, nullptr, ND, ND, 1.0f);
    gemm_kernel<<<dim3(ND / 128, M / 128, 1), 256, GEMM_SMEM>>>(
        vh, vl, 0, Wvh, Wvl, 0, nullptr, vph, vpl, 0, bv, nullptr, ND, ND, 1.0f);

    // vp -> vp^T per batch (for NT A·V GEMM)
    transpose_kernel<<<dim3(ND / 32, NL / 32, NB), 256>>>(vph, vpl, vpth, vptl);

    // scores: att[b] = scale * qp[b] @ kp[b]^T
    gemm_kernel<<<dim3(NL / 128, NL / 128, NB), 256, GEMM_SMEM>>>(
        qph, qpl, sQK, kph, kpl, sQK, att, nullptr, nullptr, sAT,
        nullptr, nullptr, ND, NL, scale);

    // masked softmax + bf16 split
    softmax_kernel<<<dim3(NL, NB), 256>>>(att, atth, attl, km, qm);

    // context: ao[b] = att[b] @ vp[b]  (= att @ vpT^T)
    gemm_kernel<<<dim3(ND / 128, NL / 128, NB), 256, GEMM_SMEM>>>(
        atth, attl, sAT, vpth, vptl, sQK, nullptr, aoh, aol, sQK,
        nullptr, nullptr, NL, ND, 1.0f);

    // output projection + bias + residual (projected q)
    gemm_kernel<<<dim3(ND / 128, M / 128, 1), 256, GEMM_SMEM>>>(
        aoh, aol, 0, Woh, Wol, 0, x, nullptr, nullptr, 0, bo, qp, ND, ND, 1.0f);

    // LayerNorm -> final output
    layernorm_kernel<<<M, 256>>>(x, out);
}

// round 5
// speedup vs baseline: 3.5397x; 1.0695x over previous
#include <cuda_runtime.h>
#include <cuda_bf16.h>
#include <math_constants.h>
#include <cstdint>

#define NB 8
#define NL 2048
#define ND 1024

typedef __nv_bfloat16 bf16;

// ------------------------------ scratch ------------------------------------
__device__ bf16  g_qh[NB * NL * ND],  g_ql[NB * NL * ND];
__device__ bf16  g_kh[NB * NL * ND],  g_kl[NB * NL * ND];
__device__ bf16  g_vh[NB * NL * ND],  g_vl[NB * NL * ND];
__device__ bf16  g_Wqh[ND * ND], g_Wql[ND * ND];
__device__ bf16  g_Wkh[ND * ND], g_Wkl[ND * ND];
__device__ bf16  g_Wvh[ND * ND], g_Wvl[ND * ND];
__device__ bf16  g_Woh[ND * ND], g_Wol[ND * ND];
__device__ float g_qp[NB * NL * ND];
__device__ bf16  g_qph[NB * NL * ND], g_qpl[NB * NL * ND];
__device__ bf16  g_kph[NB * NL * ND], g_kpl[NB * NL * ND];
__device__ bf16  g_vph[NB * NL * ND], g_vpl[NB * NL * ND];
__device__ bf16  g_vpth[NB * NL * ND], g_vptl[NB * NL * ND];
__device__ float g_att[(size_t)NB * NL * NL];
__device__ bf16  g_atth[(size_t)NB * NL * NL], g_attl[(size_t)NB * NL * NL];
__device__ bf16  g_aoh[NB * NL * ND], g_aol[NB * NL * ND];
__device__ float g_x[NB * NL * ND];
__device__ unsigned char g_kmask[NB * NL];
__device__ unsigned char g_qmask[NB * NL];

// ------------------------------ helpers ------------------------------------
__device__ __forceinline__ uint32_t smem_u32(const void* p) {
    uint32_t a;
    asm("{ .reg .u64 t; cvta.to.shared.u64 t, %1; cvt.u32.u64 %0, t; }"
        : "=r"(a) : "l"(p));
    return a;
}

__device__ __forceinline__ void cpasync16(uint32_t dst, const void* src) {
    asm volatile("cp.async.cg.shared.global [%0], [%1], 16;" :: "r"(dst), "l"(src));
}

__device__ __forceinline__ void ldsm4(uint32_t* r, uint32_t addr) {
    asm volatile("ldmatrix.sync.aligned.m8n8.x4.shared.b16 {%0,%1,%2,%3}, [%4];"
                 : "=r"(r[0]), "=r"(r[1]), "=r"(r[2]), "=r"(r[3]) : "r"(addr));
}

__device__ __forceinline__ void mma16816(float* d, const uint32_t* a, const uint32_t* b) {
    asm volatile(
        "mma.sync.aligned.m16n8k16.row.col.f32.bf16.bf16.f32 "
        "{%0,%1,%2,%3}, {%4,%5,%6,%7}, {%8,%9}, {%0,%1,%2,%3};"
        : "+f"(d[0]), "+f"(d[1]), "+f"(d[2]), "+f"(d[3])
        : "r"(a[0]), "r"(a[1]), "r"(a[2]), "r"(a[3]), "r"(b[0]), "r"(b[1]));
}

// ------------------------------ GEMM ---------------------------------------
// C[M,N] = alpha * (Ahi+Alo)[M,K] @ (Bhi+Blo)[N,K]^T   (3-term bf16 split)
// CTA tile 128x128, BK=64, 8 warps (2x4), warp tile 64x32, mma m16n8k16.
// Mask-aware: mM (per m row) all-set -> bias/res-only epilogue (or skip if skipM)
//             mN (per n col) all-set -> return (no writes)
//             mK (per k idx) -> skip fully-masked 64-wide k chunks
#define STG_A_H 0u
#define STG_A_L 16384u
#define STG_B_H 32768u
#define STG_B_L 49152u
#define STG_BYTES 65536u
#define GEMM_SMEM (2u * STG_BYTES)

__device__ __forceinline__ void load_stage(
    const bf16* __restrict__ Ah, const bf16* __restrict__ Al,
    const bf16* __restrict__ Bh, const bf16* __restrict__ Bl,
    int K, long long m0, long long n0, long long kb, uint32_t sb, int tid) {
#pragma unroll
    for (int i = 0; i < 4; i++) {
        int idx = tid + i * 256;
        int row = idx >> 3, ch = idx & 7;
        uint32_t sw = (uint32_t)(row * 128 + ((ch ^ (row & 7)) << 4));
        long long ga = (m0 + row) * K + kb + ch * 8;
        cpasync16(sb + STG_A_H + sw, Ah + ga);
        cpasync16(sb + STG_A_L + sw, Al + ga);
        long long gb = (n0 + row) * K + kb + ch * 8;
        cpasync16(sb + STG_B_H + sw, Bh + gb);
        cpasync16(sb + STG_B_L + sw, Bl + gb);
    }
    asm volatile("cp.async.commit_group;" ::: "memory");
}

__global__ __launch_bounds__(256, 1)
void gemm_kernel(const bf16* __restrict__ Ah, const bf16* __restrict__ Al, long long sA,
                 const bf16* __restrict__ Bh, const bf16* __restrict__ Bl, long long sB,
                 float* __restrict__ Cf, bf16* __restrict__ Ch, bf16* __restrict__ Cl,
                 long long sC,
                 const float* __restrict__ bias, const float* __restrict__ res,
                 int K, int ldC, float alpha,
                 const unsigned char* __restrict__ mM, long long mMs,
                 const unsigned char* __restrict__ mN, long long mNs,
                 const unsigned char* __restrict__ mK, long long mKs,
                 int skipM) {
    extern __shared__ char dsm[];
    const uint32_t sb0 = smem_u32(dsm);
    const int tid = threadIdx.x;
    const int lane = tid & 31, wid = tid >> 5;
    const int warp_m = wid >> 2, warp_n = wid & 3;
    const int bz = blockIdx.z;
    Ah += (long long)bz * sA;  Al += (long long)bz * sA;
    Bh += (long long)bz * sB;  Bl += (long long)bz * sB;
    const long long coff = (long long)bz * sC;
    const long long m0 = (long long)blockIdx.y * 128;
    const long long n0 = (long long)blockIdx.x * 128;

    // ---------------- mask checks (uniform across CTA) --------------------
    int biasOnly = 0;
    if (mM) {
        mM += (long long)bz * mMs;
        int v = (tid < 128) ? (int)mM[m0 + tid] : 1;
        biasOnly = __syncthreads_and(v);
        if (biasOnly && skipM) return;
    }
    if (!biasOnly && mN) {
        mN += (long long)bz * mNs;
        int v = (tid < 128) ? (int)mN[n0 + tid] : 1;
        if (__syncthreads_and(v)) return;
    }

    // ---------------- active k-chunk list ----------------------------------
    __shared__ int s_list[32];
    __shared__ int s_cnt;
    const int nchunks = K >> 6;
    if (!biasOnly) {
        if (mK) {
            mK += (long long)bz * mKs;
            __shared__ int s_flags[32];
            if (tid < nchunks) {
                const uint4* p = (const uint4*)(mK + tid * 64);
                uint4 x0 = p[0], x1 = p[1], x2 = p[2], x3 = p[3];
                uint32_t andall = x0.x & x0.y & x0.z & x0.w
                                & x1.x & x1.y & x1.z & x1.w
                                & x2.x & x2.y & x2.z & x2.w
                                & x3.x & x3.y & x3.z & x3.w;
                s_flags[tid] = (andall == 0x01010101u);
            }
            __syncthreads();
            if (tid == 0) {
                int n = 0;
                for (int c = 0; c < nchunks; c++)
                    if (!s_flags[c]) s_list[n++] = c;
                s_cnt = n;
            }
            __syncthreads();
        } else {
            if (tid < nchunks) s_list[tid] = tid;
            if (tid == 0) s_cnt = nchunks;
            __syncthreads();
        }
    }

    float acc[4][4][4];
#pragma unroll
    for (int a = 0; a < 4; a++)
#pragma unroll
        for (int b = 0; b < 4; b++)
#pragma unroll
            for (int c = 0; c < 4; c++) acc[a][b][c] = 0.0f;

    // lane-invariant fragment addressing
    const int aRow = warp_m * 64 + ((lane >> 3) & 1) * 8 + (lane & 7);
    const int aSel = lane >> 4;          // 0/1 -> k chunk
    const int bRow = warp_n * 32 + (lane >> 4) * 8 + (lane & 7);
    const int bSel = (lane >> 3) & 1;    // 0/1 -> k chunk

    const int cnt = biasOnly ? 0 : s_cnt;
    if (cnt > 0) {
        load_stage(Ah, Al, Bh, Bl, K, m0, n0, (long long)s_list[0] * 64, sb0, tid);
        for (int i = 0; i < cnt; i++) {
            const uint32_t sb = sb0 + (uint32_t)(i & 1) * STG_BYTES;
            if (i + 1 < cnt) {
                load_stage(Ah, Al, Bh, Bl, K, m0, n0, (long long)s_list[i + 1] * 64,
                           sb0 + (uint32_t)((i + 1) & 1) * STG_BYTES, tid);
                asm volatile("cp.async.wait_group 1;" ::: "memory");
            } else {
                asm volatile("cp.async.wait_group 0;" ::: "memory");
            }
            __syncthreads();

#pragma unroll
            for (int s = 0; s < 4; s++) {
                uint32_t ah[4][4], al[4][4], bh[2][4], bl[2][4];
#pragma unroll
                for (int mt = 0; mt < 4; mt++) {
                    int r = aRow + mt * 16;
                    uint32_t a = sb + (uint32_t)(r * 128 + (((2 * s + aSel) ^ (r & 7)) << 4));
                    ldsm4(ah[mt], a + STG_A_H);
                    ldsm4(al[mt], a + STG_A_L);
                }
#pragma unroll
                for (int p = 0; p < 2; p++) {
                    int r = bRow + p * 16;
                    uint32_t a = sb + (uint32_t)(r * 128 + (((2 * s + bSel) ^ (r & 7)) << 4));
                    ldsm4(bh[p], a + STG_B_H);
                    ldsm4(bl[p], a + STG_B_L);
                }
#pragma unroll
                for (int mt = 0; mt < 4; mt++)
#pragma unroll
                    for (int nt = 0; nt < 4; nt++) {
                        const uint32_t* Bhp = &bh[nt >> 1][(nt & 1) * 2];
                        const uint32_t* Blp = &bl[nt >> 1][(nt & 1) * 2];
                        mma16816(acc[mt][nt], ah[mt], Bhp);   // hi*hi
                        mma16816(acc[mt][nt], ah[mt], Blp);   // hi*lo
                        mma16816(acc[mt][nt], al[mt], Bhp);   // lo*hi
                    }
            }
            __syncthreads();
        }
    }

    // ---------------- epilogue -------------------------------------------
    const int g = lane >> 2, t = lane & 3;
#pragma unroll
    for (int mt = 0; mt < 4; mt++) {
#pragma unroll
        for (int nt = 0; nt < 4; nt++) {
            float* d = acc[mt][nt];
            int row0 = (int)m0 + warp_m * 64 + mt * 16 + g;
            int col  = (int)n0 + warp_n * 32 + nt * 8 + t * 2;
            float v0 = d[0] * alpha, v1 = d[1] * alpha;
            float v2 = d[2] * alpha, v3 = d[3] * alpha;
            if (bias) {
                float b0 = bias[col], b1 = bias[col + 1];
                v0 += b0; v1 += b1; v2 += b0; v3 += b1;
            }
            long long o0 = coff + (long long)row0 * ldC + col;
            long long o1 = o0 + 8LL * ldC;
            if (res) {
                v0 += res[o0]; v1 += res[o0 + 1];
                v2 += res[o1]; v3 += res[o1 + 1];
            }
            if (Cf) {
                *(float2*)(Cf + o0) = make_float2(v0, v1);
                *(float2*)(Cf + o1) = make_float2(v2, v3);
            }
            if (Ch) {
                __nv_bfloat162 h0, h1, l0, l1;
                h0.x = __float2bfloat16(v0); h0.y = __float2bfloat16(v1);
                h1.x = __float2bfloat16(v2); h1.y = __float2bfloat16(v3);
                l0.x = __float2bfloat16(v0 - __bfloat162float(h0.x));
                l0.y = __float2bfloat16(v1 - __bfloat162float(h0.y));
                l1.x = __float2bfloat16(v2 - __bfloat162float(h1.x));
                l1.y = __float2bfloat16(v3 - __bfloat162float(h1.y));
                *(__nv_bfloat162*)(Ch + o0) = h0;
                *(__nv_bfloat162*)(Ch + o1) = h1;
                *(__nv_bfloat162*)(Cl + o0) = l0;
                *(__nv_bfloat162*)(Cl + o1) = l1;
            }
        }
    }
}

// ---------------- fp32 -> bf16 hi/lo split ---------------------------------
__global__ __launch_bounds__(256)
void split_kernel(const float* __restrict__ x, bf16* __restrict__ h,
                  bf16* __restrict__ l, long long n) {
    long long i = ((long long)blockIdx.x * 256 + threadIdx.x) * 4;
    if (i >= n) return;
    float4 v = *(const float4*)(x + i);
    bf16 hh[4], ll[4];
    float vv[4] = {v.x, v.y, v.z, v.w};
#pragma unroll
    for (int j = 0; j < 4; j++) {
        hh[j] = __float2bfloat16(vv[j]);
        ll[j] = __float2bfloat16(vv[j] - __bfloat162float(hh[j]));
    }
    *(uint2*)(h + i) = *(uint2*)hh;
    *(uint2*)(l + i) = *(uint2*)ll;
}

// ---------------- masks from raw q/k (rowsum == 0) --------------------------
__global__ __launch_bounds__(256)
void mask_kernel(const float* __restrict__ q, const float* __restrict__ k,
                 unsigned char* __restrict__ qm, unsigned char* __restrict__ km) {
    int r = blockIdx.x;
    int tid = threadIdx.x;
    const float4* qr = (const float4*)(q + (long long)r * ND);
    const float4* kr = (const float4*)(k + (long long)r * ND);
    float sq = 0.f, sk = 0.f;
    for (int i = tid; i < ND / 4; i += 256) {
        float4 a = qr[i]; sq += (a.x + a.y) + (a.z + a.w);
        float4 b = kr[i]; sk += (b.x + b.y) + (b.z + b.w);
    }
    __shared__ float rq[256], rk[256];
    rq[tid] = sq; rk[tid] = sk;
    __syncthreads();
    for (int s = 128; s > 0; s >>= 1) {
        if (tid < s) { rq[tid] += rq[tid + s]; rk[tid] += rk[tid + s]; }
        __syncthreads();
    }
    if (tid == 0) {
        qm[r] = (rq[0] == 0.0f) ? 1 : 0;
        km[r] = (rk[0] == 0.0f) ? 1 : 0;
    }
}

// ---------------- masked softmax + bf16 split output ------------------------
__global__ __launch_bounds__(256)
void softmax_kernel(const float* __restrict__ att,
                    bf16* __restrict__ atth, bf16* __restrict__ attl,
                    const unsigned char* __restrict__ km,
                    const unsigned char* __restrict__ qm) {
    int i = blockIdx.x;
    int b = blockIdx.y;
    int tid = threadIdx.x;
    const float* row = att + ((long long)b * NL + i) * NL;
    bf16* oh = atth + ((long long)b * NL + i) * NL;
    bf16* ol = attl + ((long long)b * NL + i) * NL;
    const unsigned char* kmb = km + b * NL;
    bool qz = qm[b * NL + i] != 0;

    if (qz) {   // masked q row: output is exactly zero, never read scores
        uint4 z = make_uint4(0, 0, 0, 0);
        ((uint4*)oh)[tid] = z;     // 256 threads * 16B == 4096B == NL bf16
        ((uint4*)ol)[tid] = z;
        return;
    }

    float vals[NL / 256];
    float mx = -CUDART_INF_F;
#pragma unroll
    for (int t = 0; t < NL / 256; t++) {
        int j = tid + t * 256;
        float v = kmb[j] ? -CUDART_INF_F : row[j];
        vals[t] = v;
        mx = fmaxf(mx, v);
    }
    __shared__ float red[256];
    red[tid] = mx;
    __syncthreads();
    for (int s = 128; s > 0; s >>= 1) {
        if (tid < s) red[tid] = fmaxf(red[tid], red[tid + s]);
        __syncthreads();
    }
    mx = red[0];
    __syncthreads();

    float sum = 0.f;
#pragma unroll
    for (int t = 0; t < NL / 256; t++) {
        float e = __expf(vals[t] - mx);
        vals[t] = e;
        sum += e;
    }
    red[tid] = sum;
    __syncthreads();
    for (int s = 128; s > 0; s >>= 1) {
        if (tid < s) red[tid] += red[tid + s];
        __syncthreads();
    }
    float inv = 1.0f / red[0];
#pragma unroll
    for (int t = 0; t < NL / 256; t++) {
        int j = tid + t * 256;
        float v = vals[t] * inv;
        bf16 h = __float2bfloat16(v);
        bf16 l = __float2bfloat16(v - __bfloat162float(h));
        oh[j] = h;
        ol[j] = l;
    }
}

// ---------------- per-batch transpose of vp hi/lo ---------------------------
__global__ __launch_bounds__(256)
void transpose_kernel(const bf16* __restrict__ h, const bf16* __restrict__ l,
                      bf16* __restrict__ th, bf16* __restrict__ tl) {
    __shared__ bf16 sh[32][33], sl[32][33];
    int b = blockIdx.z;
    int n0 = blockIdx.x * 32;
    int l0 = blockIdx.y * 32;
    int tx = threadIdx.x & 31;
    int ty = threadIdx.x >> 5;   // 0..7
#pragma unroll
    for (int i = 0; i < 4; i++) {
        int r = ty + i * 8;
        long long src = ((long long)b * NL + l0 + r) * ND + n0 + tx;
        sh[r][tx] = h[src];
        sl[r][tx] = l[src];
    }
    __syncthreads();
#pragma unroll
    for (int i = 0; i < 4; i++) {
        int r = ty + i * 8;
        long long dst = (long long)b * ND * NL + (long long)(n0 + r) * NL + l0 + tx;
        th[dst] = sh[tx][r];
        tl[dst] = sl[tx][r];
    }
}

// ---------------- LayerNorm (no affine), row length 1024 --------------------
__global__ __launch_bounds__(256)
void layernorm_kernel(const float* __restrict__ x, float* __restrict__ out) {
    int r = blockIdx.x;
    int tid = threadIdx.x;
    const float4* xr = (const float4*)(x + (long long)r * ND);
    float4 v = xr[tid];
    __shared__ float red[256];

    red[tid] = (v.x + v.y) + (v.z + v.w);
    __syncthreads();
    for (int s = 128; s > 0; s >>= 1) {
        if (tid < s) red[tid] += red[tid + s];
        __syncthreads();
    }
    float mu = red[0] * (1.0f / ND);
    __syncthreads();

    float dx = v.x - mu, dy = v.y - mu, dz = v.z - mu, dw = v.w - mu;
    red[tid] = dx * dx + dy * dy + dz * dz + dw * dw;
    __syncthreads();
    for (int s = 128; s > 0; s >>= 1) {
        if (tid < s) red[tid] += red[tid + s];
        __syncthreads();
    }
    float inv = rsqrtf(red[0] * (1.0f / ND) + 1e-5f);

    float4 o;
    o.x = dx * inv; o.y = dy * inv; o.z = dz * inv; o.w = dw * inv;
    ((float4*)(out + (long long)r * ND))[tid] = o;
}

// ---------------- launch -----------------------------------------------------
extern "C" void kernel_launch(void* const* d_in, const int* in_sizes, int n_in,
                              void* d_out, int out_size) {
    const float* q  = (const float*)d_in[0];
    const float* k  = (const float*)d_in[1];
    const float* v  = (const float*)d_in[2];
    const float* Wq = (const float*)d_in[3];
    const float* bq = (const float*)d_in[4];
    const float* Wk = (const float*)d_in[5];
    const float* bk = (const float*)d_in[6];
    const float* Wv = (const float*)d_in[7];
    const float* bv = (const float*)d_in[8];
    const float* Wo = (const float*)d_in[9];
    const float* bo = (const float*)d_in[10];
    float* out = (float*)d_out;

    bf16 *qh, *ql, *kh, *kl, *vh, *vl;
    bf16 *Wqh, *Wql, *Wkh, *Wkl, *Wvh, *Wvl, *Woh, *Wol;
    float *qp, *att, *x;
    bf16 *qph, *qpl, *kph, *kpl, *vph, *vpl, *vpth, *vptl, *atth, *attl, *aoh, *aol;
    unsigned char *km, *qm;
    cudaGetSymbolAddress((void**)&qh,  g_qh);   cudaGetSymbolAddress((void**)&ql,  g_ql);
    cudaGetSymbolAddress((void**)&kh,  g_kh);   cudaGetSymbolAddress((void**)&kl,  g_kl);
    cudaGetSymbolAddress((void**)&vh,  g_vh);   cudaGetSymbolAddress((void**)&vl,  g_vl);
    cudaGetSymbolAddress((void**)&Wqh, g_Wqh);  cudaGetSymbolAddress((void**)&Wql, g_Wql);
    cudaGetSymbolAddress((void**)&Wkh, g_Wkh);  cudaGetSymbolAddress((void**)&Wkl, g_Wkl);
    cudaGetSymbolAddress((void**)&Wvh, g_Wvh);  cudaGetSymbolAddress((void**)&Wvl, g_Wvl);
    cudaGetSymbolAddress((void**)&Woh, g_Woh);  cudaGetSymbolAddress((void**)&Wol, g_Wol);
    cudaGetSymbolAddress((void**)&qp,  g_qp);
    cudaGetSymbolAddress((void**)&qph, g_qph);  cudaGetSymbolAddress((void**)&qpl, g_qpl);
    cudaGetSymbolAddress((void**)&kph, g_kph);  cudaGetSymbolAddress((void**)&kpl, g_kpl);
    cudaGetSymbolAddress((void**)&vph, g_vph);  cudaGetSymbolAddress((void**)&vpl, g_vpl);
    cudaGetSymbolAddress((void**)&vpth, g_vpth); cudaGetSymbolAddress((void**)&vptl, g_vptl);
    cudaGetSymbolAddress((void**)&att, g_att);
    cudaGetSymbolAddress((void**)&atth, g_atth); cudaGetSymbolAddress((void**)&attl, g_attl);
    cudaGetSymbolAddress((void**)&aoh, g_aoh);  cudaGetSymbolAddress((void**)&aol, g_aol);
    cudaGetSymbolAddress((void**)&x,   g_x);
    cudaGetSymbolAddress((void**)&km,  g_kmask); cudaGetSymbolAddress((void**)&qm, g_qmask);

    cudaFuncSetAttribute(gemm_kernel, cudaFuncAttributeMaxDynamicSharedMemorySize, GEMM_SMEM);

    const long long E  = (long long)NB * NL * ND;   // 16,777,216
    const long long EW = (long long)ND * ND;        // 1,048,576
    const int M = NB * NL;                          // 16384
    const long long sQK = (long long)NL * ND;
    const long long sAT = (long long)NL * NL;
    const float scale = 0.03125f;                   // 1024^-0.5

    // masks
    mask_kernel<<<M, 256>>>(q, k, qm, km);

    // fp32 -> bf16 hi/lo splits of inputs and weights
    split_kernel<<<(int)(E / 4 / 256), 256>>>(q, qh, ql, E);
    split_kernel<<<(int)(E / 4 / 256), 256>>>(k, kh, kl, E);
    split_kernel<<<(int)(E / 4 / 256), 256>>>(v, vh, vl, E);
    split_kernel<<<(int)(EW / 4 / 256), 256>>>(Wq, Wqh, Wql, EW);
    split_kernel<<<(int)(EW / 4 / 256), 256>>>(Wk, Wkh, Wkl, EW);
    split_kernel<<<(int)(EW / 4 / 256), 256>>>(Wv, Wvh, Wvl, EW);
    split_kernel<<<(int)(EW / 4 / 256), 256>>>(Wo, Woh, Wol, EW);

    // projections: y = x @ W^T + b   (masked rows -> bias only)
    gemm_kernel<<<dim3(ND / 128, M / 128, 1), 256, GEMM_SMEM>>>(
        qh, ql, 0, Wqh, Wql, 0, qp, qph, qpl, 0, bq, nullptr, ND, ND, 1.0f,
        qm, 0, nullptr, 0, nullptr, 0, 0);
    gemm_kernel<<<dim3(ND / 128, M / 128, 1), 256, GEMM_SMEM>>>(
        kh, kl, 0, Wkh, Wkl, 0, nullptr, kph, kpl, 0, bk, nullptr, ND, ND, 1.0f,
        km, 0, nullptr, 0, nullptr, 0, 0);
    gemm_kernel<<<dim3(ND / 128, M / 128, 1), 256, GEMM_SMEM>>>(
        vh, vl, 0, Wvh, Wvl, 0, nullptr, vph, vpl, 0, bv, nullptr, ND, ND, 1.0f,
        km, 0, nullptr, 0, nullptr, 0, 0);

    // vp -> vp^T per batch (for NT A·V GEMM)
    transpose_kernel<<<dim3(ND / 32, NL / 32, NB), 256>>>(vph, vpl, vpth, vptl);

    // scores: att[b] = scale * qp[b] @ kp[b]^T  (skip all-masked q/k tiles)
    gemm_kernel<<<dim3(NL / 128, NL / 128, NB), 256, GEMM_SMEM>>>(
        qph, qpl, sQK, kph, kpl, sQK, att, nullptr, nullptr, sAT,
        nullptr, nullptr, ND, NL, scale,
        qm, NL, km, NL, nullptr, 0, 1);

    // masked softmax + bf16 split (masked q rows -> zero, no reads)
    softmax_kernel<<<dim3(NL, NB), 256>>>(att, atth, attl, km, qm);

    // context: ao[b] = att[b] @ vp[b]  (skip masked q tiles + masked k chunks)
    gemm_kernel<<<dim3(ND / 128, NL / 128, NB), 256, GEMM_SMEM>>>(
        atth, attl, sAT, vpth, vptl, sQK, nullptr, aoh, aol, sQK,
        nullptr, nullptr, NL, ND, 1.0f,
        qm, NL, nullptr, 0, km, NL, 0);

    // output projection + bias + residual (projected q); masked rows -> bo+qp
    gemm_kernel<<<dim3(ND / 128, M / 128, 1), 256, GEMM_SMEM>>>(
        aoh, aol, 0, Woh, Wol, 0, x, nullptr, nullptr, 0, bo, qp, ND, ND, 1.0f,
        qm, 0, nullptr, 0, nullptr, 0, 0);

    // LayerNorm -> final output
    layernorm_kernel<<<M, 256>>>(x, out);
}